// round 14
// baseline (speedup 1.0000x reference)
#include <cuda_runtime.h>
#include <cuda_bf16.h>
#include <math.h>
#include <stdint.h>

// ---------------------------------------------------------------------------
// Problem constants
// ---------------------------------------------------------------------------
#define BB   8        // batch
#define PP   1024     // points
#define FIN  64
#define MM   160      // multiplicity
#define DOUT 5120
#define TOTAL_K 2560
#define MID  32
#define RWID 10240    // M*FIN

// ---------------------------------------------------------------------------
// Scratch (static device globals; no allocations allowed)
// ---------------------------------------------------------------------------
__device__ float g_R    [3*4*BB*RWID];                 // radial outputs  (3.75 MB)
__device__ float g_kernT[(size_t)3*BB*TOTAL_K*FIN];    // kernels^T       (15.7 MB)
__device__ float g_qkv  [(size_t)3*BB*PP*TOTAL_K];     // q/k/v           (252 MB)
__device__ float g_vT   [(size_t)BB*TOTAL_K*PP];       // v transposed    (84 MB)
__device__ float g_trT  [(size_t)BB*DOUT*FIN];         // transform^T     (10.5 MB)
__device__ float g_e    [(size_t)BB*PP*PP];            // attn scores     (33.5 MB)
__device__ float g_z    [(size_t)BB*PP*TOTAL_K];       // attn output     (84 MB)
__device__ float g_y    [(size_t)BB*PP*DOUT];          // post-Wl1        (168 MB)

// ---------------------------------------------------------------------------
// TF32 helpers
// ---------------------------------------------------------------------------
__device__ __forceinline__ unsigned f2tf(float x) {
    unsigned r;
    asm("cvt.rna.tf32.f32 %0, %1;" : "=r"(r) : "f"(x));
    return r;
}
__device__ __forceinline__ void split4(float4 v, uint4& hi, uint4& lo) {
    hi.x = f2tf(v.x); lo.x = f2tf(v.x - __uint_as_float(hi.x));
    hi.y = f2tf(v.y); lo.y = f2tf(v.y - __uint_as_float(hi.y));
    hi.z = f2tf(v.z); lo.z = f2tf(v.z - __uint_as_float(hi.z));
    hi.w = f2tf(v.w); lo.w = f2tf(v.w - __uint_as_float(hi.w));
}
__device__ __forceinline__ void mma_tf32(float c[4], const unsigned a[4],
                                         const unsigned b[2]) {
    asm volatile(
        "mma.sync.aligned.m16n8k8.row.col.f32.tf32.tf32.f32 "
        "{%0,%1,%2,%3}, {%4,%5,%6,%7}, {%8,%9}, {%0,%1,%2,%3};"
        : "+f"(c[0]), "+f"(c[1]), "+f"(c[2]), "+f"(c[3])
        : "r"(a[0]), "r"(a[1]), "r"(a[2]), "r"(a[3]), "r"(b[0]), "r"(b[1]));
}

// ---------------------------------------------------------------------------
// 3xTF32 NT GEMM, pre-split smem (hi/lo), double-buffered, 1 sync/chunk.
// 128x128 tile, source-K chunk 16.  256 threads (8 warps 2Mx4N),
// warp = 64x32 via 4x4 m16n8k8 fragments.
// smem: 2 stages x {AsH, AsL, BsH, BsL} x 128x20 floats = 80 KB dynamic.
// Per iteration kt:  store chunk kt+1 (regs->other buf) ; MMA chunk kt ;
//                    __syncthreads ; prefetch chunk kt+2 (gmem->regs).
// A [M][K] lda, B [N][K] ldb, k-contiguous, 16B-aligned rows, M%128==0, K%16==0.
// GUARD=1: B rows >= N zero-filled; epilogue col-guarded (N even).
// C = (acc?C:0) + alpha*A.B^T + (bias?bias[n]:0)
// ---------------------------------------------------------------------------
#define KP 20
#define ELEMS (128*KP)                 // 2560 floats per array
#define GEMM_SMEM (2*4*ELEMS*4)        // 81920 bytes

template<int GUARD>
__global__ __launch_bounds__(256)
void ntmma2(const float* __restrict__ A, const float* __restrict__ B,
            float* __restrict__ C,
            int M, int N, int K, int lda, int ldb, int ldc,
            long sA, long sB, long sC,
            float alpha, const float* __restrict__ bias, int acc)
{
    extern __shared__ __align__(16) unsigned sm[];

    A += (long)blockIdx.z * sA;
    B += (long)blockIdx.z * sB;
    C += (long)blockIdx.z * sC;

    const int m0 = blockIdx.y * 128;
    const int n0 = blockIdx.x * 128;
    const int tid  = threadIdx.x;
    const int lane = tid & 31;
    const int warp = tid >> 5;
    const int wm = warp & 1;        // 0..1 (64-row group)
    const int wn = warp >> 1;       // 0..3 (32-col group)
    const int g  = lane >> 2;       // 0..7
    const int t  = lane & 3;        // 0..3

    // copy coordinates: 512 float4-chunks per 128x16 tile, 2 per thread
    const int mr0 = tid >> 2,          kq0 = (tid & 3) * 4;
    const int mr1 = (tid + 256) >> 2,  kq1 = ((tid + 256) & 3) * 4;

    float c[4][4][4];
    #pragma unroll
    for (int i = 0; i < 4; i++)
        #pragma unroll
        for (int j = 0; j < 4; j++)
            #pragma unroll
            for (int k = 0; k < 4; k++) c[i][j][k] = 0.f;

    float4 pa0, pa1, pb0, pb1;                 // prefetch registers

    auto fetch = [&](int ko) {
        pa0 = *(const float4*)&A[(long)(m0 + mr0)*lda + ko + kq0];
        pa1 = *(const float4*)&A[(long)(m0 + mr1)*lda + ko + kq1];
        pb0 = make_float4(0.f, 0.f, 0.f, 0.f);
        pb1 = make_float4(0.f, 0.f, 0.f, 0.f);
        if (!GUARD || (n0 + mr0) < N)
            pb0 = *(const float4*)&B[(long)(n0 + mr0)*ldb + ko + kq0];
        if (!GUARD || (n0 + mr1) < N)
            pb1 = *(const float4*)&B[(long)(n0 + mr1)*ldb + ko + kq1];
    };
    auto store_split = [&](int s) {
        unsigned* AH = sm + (s*4 + 0)*ELEMS;
        unsigned* AL = sm + (s*4 + 1)*ELEMS;
        unsigned* BH = sm + (s*4 + 2)*ELEMS;
        unsigned* BL = sm + (s*4 + 3)*ELEMS;
        uint4 h, l;
        split4(pa0, h, l);
        *(uint4*)&AH[mr0*KP + kq0] = h;  *(uint4*)&AL[mr0*KP + kq0] = l;
        split4(pa1, h, l);
        *(uint4*)&AH[mr1*KP + kq1] = h;  *(uint4*)&AL[mr1*KP + kq1] = l;
        split4(pb0, h, l);
        *(uint4*)&BH[mr0*KP + kq0] = h;  *(uint4*)&BL[mr0*KP + kq0] = l;
        split4(pb1, h, l);
        *(uint4*)&BH[mr1*KP + kq1] = h;  *(uint4*)&BL[mr1*KP + kq1] = l;
    };

    const int KT = K / 16;

    // prologue: chunk 0 into buf 0, prefetch chunk 1
    fetch(0);
    store_split(0);
    __syncthreads();
    if (KT > 1) fetch(16);

    for (int kt = 0; kt < KT; kt++) {
        // stage chunk kt+1 into the other buffer (regs were prefetched)
        if (kt + 1 < KT) store_split((kt + 1) & 1);

        const unsigned* AH = sm + ((kt & 1)*4 + 0)*ELEMS;
        const unsigned* AL = sm + ((kt & 1)*4 + 1)*ELEMS;
        const unsigned* BH = sm + ((kt & 1)*4 + 2)*ELEMS;
        const unsigned* BL = sm + ((kt & 1)*4 + 3)*ELEMS;

        #pragma unroll
        for (int ks = 0; ks < 16; ks += 8) {
            unsigned aH[4][4], aL[4][4], bH[4][2], bL[4][2];
            #pragma unroll
            for (int mt = 0; mt < 4; mt++) {
                int am = wm*64 + mt*16;
                aH[mt][0] = AH[(am + g    )*KP + ks + t    ];
                aH[mt][1] = AH[(am + g + 8)*KP + ks + t    ];
                aH[mt][2] = AH[(am + g    )*KP + ks + t + 4];
                aH[mt][3] = AH[(am + g + 8)*KP + ks + t + 4];
                aL[mt][0] = AL[(am + g    )*KP + ks + t    ];
                aL[mt][1] = AL[(am + g + 8)*KP + ks + t    ];
                aL[mt][2] = AL[(am + g    )*KP + ks + t + 4];
                aL[mt][3] = AL[(am + g + 8)*KP + ks + t + 4];
            }
            #pragma unroll
            for (int nt = 0; nt < 4; nt++) {
                int bn = wn*32 + nt*8;
                bH[nt][0] = BH[(bn + g)*KP + ks + t    ];
                bH[nt][1] = BH[(bn + g)*KP + ks + t + 4];
                bL[nt][0] = BL[(bn + g)*KP + ks + t    ];
                bL[nt][1] = BL[(bn + g)*KP + ks + t + 4];
            }
            #pragma unroll
            for (int mt = 0; mt < 4; mt++)
                #pragma unroll
                for (int nt = 0; nt < 4; nt++) {
                    mma_tf32(c[mt][nt], aH[mt], bL[nt]);
                    mma_tf32(c[mt][nt], aL[mt], bH[nt]);
                    mma_tf32(c[mt][nt], aH[mt], bH[nt]);
                }
        }
        // one sync: my reads of buf[kt&1] done AND my stores of buf[(kt+1)&1]
        // visible before the next iteration touches either.
        __syncthreads();
        if (kt + 2 < KT) fetch((kt + 2) * 16);
    }

    // ---- epilogue ----
    #pragma unroll
    for (int mt = 0; mt < 4; mt++) {
        #pragma unroll
        for (int nt = 0; nt < 4; nt++) {
            int col = n0 + wn*32 + nt*8 + t*2;
            if (GUARD && col >= N) continue;   // N even, col even -> pair safe
            #pragma unroll
            for (int h = 0; h < 2; h++) {
                int row = m0 + wm*64 + mt*16 + g + h*8;
                float v0 = c[mt][nt][h*2 + 0] * alpha;
                float v1 = c[mt][nt][h*2 + 1] * alpha;
                long off = (long)row*ldc + col;
                if (bias) { v0 += bias[col]; v1 += bias[col + 1]; }
                if (acc) {
                    float2 c2 = *(const float2*)&C[off];
                    v0 += c2.x; v1 += c2.y;
                }
                float2 o2; o2.x = v0; o2.y = v1;
                *(float2*)&C[off] = o2;
            }
        }
    }
}

// ---------------------------------------------------------------------------
// Kernel 1: stacked radial MLPs.  One block per (t,g,b) = 96 blocks.
// ---------------------------------------------------------------------------
__global__ void radial_kernel(const float* __restrict__ r,
                              const float* __restrict__ W1, const float* __restrict__ b1,
                              const float* __restrict__ g1, const float* __restrict__ be1,
                              const float* __restrict__ W2, const float* __restrict__ b2,
                              const float* __restrict__ g2, const float* __restrict__ be2,
                              const float* __restrict__ W3, const float* __restrict__ b3,
                              float* __restrict__ R)
{
    int id  = blockIdx.x;     // tg*8 + b
    int b   = id & 7;
    int tg  = id >> 3;        // t*4+g
    int tid = threadIdx.x;
    float rb = r[b];          // r is [B,1]

    __shared__ float h1[32], h2[32];

    if (tid < 32) {
        float v = rb * W1[tg*32 + tid] + b1[tg*32 + tid];
        float mu = v;
        #pragma unroll
        for (int o = 16; o; o >>= 1) mu += __shfl_xor_sync(0xffffffffu, mu, o);
        mu *= (1.f/32.f);
        float d = v - mu;
        float var = d*d;
        #pragma unroll
        for (int o = 16; o; o >>= 1) var += __shfl_xor_sync(0xffffffffu, var, o);
        var *= (1.f/32.f);
        float x = d * rsqrtf(var + 1e-5f) * g1[tg*32 + tid] + be1[tg*32 + tid];
        h1[tid] = fmaxf(x, 0.f);
    }
    __syncthreads();

    if (tid < 32) {
        float acc = b2[tg*32 + tid];
        const float* w = W2 + ((size_t)tg*32 + tid) * 32;
        #pragma unroll
        for (int i = 0; i < 32; i++) acc += h1[i] * w[i];
        float mu = acc;
        #pragma unroll
        for (int o = 16; o; o >>= 1) mu += __shfl_xor_sync(0xffffffffu, mu, o);
        mu *= (1.f/32.f);
        float d = acc - mu;
        float var = d*d;
        #pragma unroll
        for (int o = 16; o; o >>= 1) var += __shfl_xor_sync(0xffffffffu, var, o);
        var *= (1.f/32.f);
        float x = d * rsqrtf(var + 1e-5f) * g2[tg*32 + tid] + be2[tg*32 + tid];
        h2[tid] = fmaxf(x, 0.f);
    }
    __syncthreads();

    for (int o = tid; o < RWID; o += blockDim.x) {
        float acc = b3[(size_t)tg*RWID + o];
        const float* w = W3 + ((size_t)tg*RWID + o) * 32;
        #pragma unroll
        for (int i = 0; i < 32; i++) acc += h2[i] * w[i];
        R[(size_t)id*RWID + o] = acc;
    }
}

// ---------------------------------------------------------------------------
// Kernel 2: build kernT[t,b,ktot,i] (transposed kernel, NT-friendly)
// ---------------------------------------------------------------------------
__global__ void build_kernT(const float* __restrict__ R,
                            const float* __restrict__ bas0, const float* __restrict__ bas1,
                            const float* __restrict__ bas2, const float* __restrict__ bas3,
                            float* __restrict__ kernT)
{
    long idx = (long)blockIdx.x * blockDim.x + threadIdx.x;
    const long total = 3L * BB * TOTAL_K * FIN;
    if (idx >= total) return;

    int i = (int)(idx % FIN);
    long rem = idx / FIN;
    int ktot = (int)(rem % TOTAL_K);
    rem /= TOTAL_K;
    int b = (int)(rem % BB);
    int t = (int)(rem / BB);

    int g, k0, dout;
    const float* bas;
    if      (ktot < 160)  { g = 0; k0 = 0;    dout = 1; bas = bas0; }
    else if (ktot < 640)  { g = 1; k0 = 160;  dout = 3; bas = bas1; }
    else if (ktot < 1440) { g = 2; k0 = 640;  dout = 5; bas = bas2; }
    else                  { g = 3; k0 = 1440; dout = 7; bas = bas3; }

    int kg  = ktot - k0;
    int lin = i * (MM * dout) + kg;
    int mo  = lin / (dout * FIN);
    int j   = (lin / FIN) % dout;
    int mi  = lin % FIN;

    float v = R[((size_t)((t*4 + g)*BB + b))*RWID + mo*FIN + mi] * bas[b*dout + j];
    kernT[idx] = v;
}

// ---------------------------------------------------------------------------
// Batched 32x32 tiled transpose: in [b][R][C] -> out [b][C][R].
// ---------------------------------------------------------------------------
__global__ void transpose_bat(const float* __restrict__ in, float* __restrict__ out,
                              int R, int C, long sIn, long sOut)
{
    __shared__ float tile[32][33];
    const float* ip = in  + (long)blockIdx.z * sIn;
    float*       op = out + (long)blockIdx.z * sOut;

    int c0 = blockIdx.x * 32, r0 = blockIdx.y * 32;
    int tx = threadIdx.x, ty = threadIdx.y;

    #pragma unroll
    for (int i = 0; i < 32; i += 8)
        tile[ty + i][tx] = ip[(long)(r0 + ty + i)*C + c0 + tx];
    __syncthreads();
    #pragma unroll
    for (int i = 0; i < 32; i += 8)
        op[(long)(c0 + ty + i)*R + r0 + tx] = tile[tx][ty + i];
}

// ---------------------------------------------------------------------------
// Softmax over axis p (rows) for each column q, in place.
// ---------------------------------------------------------------------------
__global__ void col_softmax(float* __restrict__ e)
{
    int b = blockIdx.y;
    int q = blockIdx.x * blockDim.x + threadIdx.x;   // 0..1023
    float* base = e + (size_t)b * PP * PP + q;

    float m = -INFINITY, s = 0.f;
    for (int p = 0; p < PP; p++) {
        float v  = base[(size_t)p * PP];
        float nm = fmaxf(m, v);
        s = s * __expf(m - nm) + __expf(v - nm);
        m = nm;
    }
    float inv = 1.f / s;
    for (int p = 0; p < PP; p++) {
        size_t off = (size_t)p * PP;
        base[off] = __expf(base[off] - m) * inv;
    }
}

// ---------------------------------------------------------------------------
// Row LayerNorm over 5120 + ReLU, in place. One block per row.
// ---------------------------------------------------------------------------
__global__ __launch_bounds__(256)
void ln_relu(float* __restrict__ y, const float* __restrict__ gg,
             const float* __restrict__ bb)
{
    long row = blockIdx.x;
    float* p = y + row * DOUT;
    int tid = threadIdx.x;

    float v[20];
    float s = 0.f;
    #pragma unroll
    for (int j = 0; j < 20; j++) { v[j] = p[tid + j*256]; s += v[j]; }

    __shared__ float red[256];
    red[tid] = s; __syncthreads();
    #pragma unroll
    for (int st = 128; st; st >>= 1) {
        if (tid < st) red[tid] += red[tid + st];
        __syncthreads();
    }
    float mu = red[0] * (1.f / DOUT);
    __syncthreads();

    float qs = 0.f;
    #pragma unroll
    for (int j = 0; j < 20; j++) { float d = v[j] - mu; qs += d*d; }
    red[tid] = qs; __syncthreads();
    #pragma unroll
    for (int st = 128; st; st >>= 1) {
        if (tid < st) red[tid] += red[tid + st];
        __syncthreads();
    }
    float is = rsqrtf(red[0] * (1.f / DOUT) + 1e-5f);

    #pragma unroll
    for (int j = 0; j < 20; j++) {
        int o = tid + j*256;
        float x = (v[j] - mu) * is * gg[o] + bb[o];
        p[o] = fmaxf(x, 0.f);
    }
}

// ---------------------------------------------------------------------------
// Launch
// ---------------------------------------------------------------------------
extern "C" void kernel_launch(void* const* d_in, const int* in_sizes, int n_in,
                              void* d_out, int out_size)
{
    const float* f     = (const float*)d_in[0];   // [8,1024,64]
    const float* r     = (const float*)d_in[1];   // [8,1]
    const float* bas0  = (const float*)d_in[2];
    const float* bas1  = (const float*)d_in[3];
    const float* bas2  = (const float*)d_in[4];
    const float* bas3  = (const float*)d_in[5];
    const float* W1    = (const float*)d_in[6];
    const float* b1    = (const float*)d_in[7];
    const float* g1    = (const float*)d_in[8];
    const float* be1   = (const float*)d_in[9];
    const float* W2    = (const float*)d_in[10];
    const float* b2    = (const float*)d_in[11];
    const float* g2    = (const float*)d_in[12];
    const float* be2   = (const float*)d_in[13];
    const float* W3    = (const float*)d_in[14];
    const float* b3    = (const float*)d_in[15];
    const float* trans = (const float*)d_in[16];  // [8,64,5120]
    const float* Wl1   = (const float*)d_in[17];  // [5120,2560]
    const float* bl1   = (const float*)d_in[18];
    const float* ln_g  = (const float*)d_in[19];
    const float* ln_b  = (const float*)d_in[20];
    const float* Wl2   = (const float*)d_in[21];  // [5120,5120]
    const float* bl2   = (const float*)d_in[22];
    float* out = (float*)d_out;

    float *R, *kernT, *qkv, *vT, *trT, *e, *z, *y;
    cudaGetSymbolAddress((void**)&R,     g_R);
    cudaGetSymbolAddress((void**)&kernT, g_kernT);
    cudaGetSymbolAddress((void**)&qkv,   g_qkv);
    cudaGetSymbolAddress((void**)&vT,    g_vT);
    cudaGetSymbolAddress((void**)&trT,   g_trT);
    cudaGetSymbolAddress((void**)&e,     g_e);
    cudaGetSymbolAddress((void**)&z,     g_z);
    cudaGetSymbolAddress((void**)&y,     g_y);

    // opt in to 80 KB dynamic smem for the GEMM (idempotent, host-side)
    cudaFuncSetAttribute(ntmma2<0>, cudaFuncAttributeMaxDynamicSharedMemorySize, GEMM_SMEM);
    cudaFuncSetAttribute(ntmma2<1>, cudaFuncAttributeMaxDynamicSharedMemorySize, GEMM_SMEM);

    // 1) radial MLPs -> R
    radial_kernel<<<96, 256>>>(r, W1, b1, g1, be1, W2, b2, g2, be2, W3, b3, R);

    // 2) kernels (transposed: [t,b,ktot,i])
    {
        long total = 3L * BB * TOTAL_K * FIN;
        build_kernT<<<(unsigned)((total + 255) / 256), 256>>>(R, bas0, bas1, bas2, bas3, kernT);
    }

    // 3) qkv[t,b] = f[b] @ kernT[t,b]^T   (NT: M=1024, N=2560, K=64)
    for (int t = 0; t < 3; t++) {
        dim3 grid(TOTAL_K/128, PP/128, BB);
        ntmma2<0><<<grid, 256, GEMM_SMEM>>>(f,
                                kernT + (long)t*BB*TOTAL_K*FIN,
                                qkv   + (long)t*BB*PP*TOTAL_K,
                                PP, TOTAL_K, FIN, FIN, FIN, TOTAL_K,
                                (long)PP*FIN, (long)TOTAL_K*FIN, (long)PP*TOTAL_K,
                                1.f, nullptr, 0);
    }

    // 4) transpose v -> vT  ([b,1024,2560] -> [b,2560,1024])
    transpose_bat<<<dim3(TOTAL_K/32, PP/32, BB), dim3(32, 8)>>>(
        qkv, vT, PP, TOTAL_K, (long)PP*TOTAL_K, (long)TOTAL_K*PP);

    // 5) transpose transform -> trT  ([b,64,5120] -> [b,5120,64])
    transpose_bat<<<dim3(DOUT/32, FIN/32, BB), dim3(32, 8)>>>(
        trans, trT, FIN, DOUT, (long)FIN*DOUT, (long)DOUT*FIN);

    const int K0[4] = {0, 160, 640, 1440};
    const int KG[4] = {160, 480, 800, 1120};

    // 6) per-degree attention, reusing one score buffer e[8,1024,1024]
    for (int g = 0; g < 4; g++) {
        // scores: e[b] = scale * Q_seg @ K_seg^T  (NT, full tiles, K=KG[g])
        {
            dim3 grid(PP/128, PP/128, BB);
            float scale = 1.0f / sqrtf((float)KG[g]);
            ntmma2<0><<<grid, 256, GEMM_SMEM>>>(qkv + 2L*BB*PP*TOTAL_K + K0[g],
                                    qkv + 1L*BB*PP*TOTAL_K + K0[g],
                                    e,
                                    PP, PP, KG[g], TOTAL_K, TOTAL_K, PP,
                                    (long)PP*TOTAL_K, (long)PP*TOTAL_K, (long)PP*PP,
                                    scale, nullptr, 0);
        }
        // softmax over p for each column q
        col_softmax<<<dim3(PP/256, BB), 256>>>(e);
        // z segment = alpha @ vT_seg^T  (NT, M=1024, N=KG[g] guarded, K=1024)
        {
            dim3 grid((KG[g] + 127)/128, PP/128, BB);
            ntmma2<1><<<grid, 256, GEMM_SMEM>>>(e,
                                    vT + (long)K0[g]*PP,
                                    z  + K0[g],
                                    PP, KG[g], PP, PP, PP, TOTAL_K,
                                    (long)PP*PP, (long)TOTAL_K*PP, (long)PP*TOTAL_K,
                                    1.f, nullptr, 0);
        }
    }

    // 7) y = z @ Wl1^T + bl1   (NT: M=8192, N=5120, K=2560)
    {
        dim3 grid(DOUT/128, (BB*PP)/128, 1);
        ntmma2<0><<<grid, 256, GEMM_SMEM>>>(z, Wl1, y,
                                BB*PP, DOUT, TOTAL_K, TOTAL_K, TOTAL_K, DOUT,
                                0, 0, 0, 1.f, bl1, 0);
    }

    // 8) LayerNorm + ReLU in place on y
    ln_relu<<<BB*PP, 256>>>(y, ln_g, ln_b);

    // 9) out = f @ trT^T + bl2   (NT per-b: M=1024, N=5120, K=64)
    {
        dim3 grid(DOUT/128, PP/128, BB);
        ntmma2<0><<<grid, 256, GEMM_SMEM>>>(f, trT, out,
                                PP, DOUT, FIN, FIN, FIN, DOUT,
                                (long)PP*FIN, (long)DOUT*FIN, (long)PP*DOUT,
                                1.f, bl2, 0);
    }

    // 10) out += y @ Wl2^T   (NT: M=8192, N=5120, K=5120)
    {
        dim3 grid(DOUT/128, (BB*PP)/128, 1);
        ntmma2<0><<<grid, 256, GEMM_SMEM>>>(y, Wl2, out,
                                BB*PP, DOUT, DOUT, DOUT, DOUT, DOUT,
                                0, 0, 0, 1.f, nullptr, 1);
    }
}